// round 3
// baseline (speedup 1.0000x reference)
#include <cuda_runtime.h>
#include <cuda_bf16.h>

// Fused symplectic integrator (leapfrog with low-rank Christoffel force):
//   per step: a = f - (v@U)^2*tanh(x@U) @ W (twice, half-kicks), torus wrap on x.
// One CTA owns ROWS rows for the whole 8-step integration. U[256x64], W[64x256],
// x/v row tiles and the intermediate p[ROWS x 64] all live in SMEM; force tile
// lives in registers. 512 threads = 16 warps/SM for latency hiding (1 CTA/SM).

#define DDIM 256
#define RDIM 64
#define ROWS 32
#define THREADS 512
#define XS_LD 264   // 256 + 8 pad, float4-aligned, conflict-free
#define PS_LD 68    // 64 + 4 pad

__device__ __forceinline__ float my_tanhf(float g) {
    // faithful tanh (~1e-6 rel), stable for all magnitudes
    float ag = fabsf(g);
    float e  = __expf(2.0f * ag);
    float t  = 1.0f - 2.0f / (e + 1.0f);
    return copysignf(t, g);
}

__device__ __forceinline__ float wrap_torus(float x) {
    const float PIf = 3.14159274101257324f;   // np.float32(np.pi)
    const float TPI = 6.28318548202514648f;   // 2*PIf
    float t = x + PIf;
    float r = fmodf(t, TPI);
    if (r < 0.0f) r += TPI;
    return r - PIf;
}

// Phase A: ps[row][n0..n0+3] = (v@U)^2 * tanh(x@U)
__device__ __forceinline__ void phaseA(const float* __restrict__ xs,
                                       const float* __restrict__ vs,
                                       float* __restrict__ ps,
                                       const float* __restrict__ U_s,
                                       int row, int n0) {
    float hacc[4] = {};
    float gacc[4] = {};
    #pragma unroll 4
    for (int k0 = 0; k0 < DDIM; k0 += 4) {
        float4 va = *(const float4*)&vs[row * XS_LD + k0];
        float4 xa = *(const float4*)&xs[row * XS_LD + k0];
        float vv[4] = {va.x, va.y, va.z, va.w};
        float xx[4] = {xa.x, xa.y, xa.z, xa.w};
        #pragma unroll
        for (int kk = 0; kk < 4; kk++) {
            float4 u = *(const float4*)&U_s[(k0 + kk) * RDIM + n0];
            float uu[4] = {u.x, u.y, u.z, u.w};
            #pragma unroll
            for (int j = 0; j < 4; j++) {
                hacc[j] += vv[kk] * uu[j];
                gacc[j] += xx[kk] * uu[j];
            }
        }
    }
    float4 pv;
    float pe[4];
    #pragma unroll
    for (int j = 0; j < 4; j++) {
        float h = hacc[j];
        pe[j] = h * h * my_tanhf(gacc[j]);
    }
    pv.x = pe[0]; pv.y = pe[1]; pv.z = pe[2]; pv.w = pe[3];
    *(float4*)&ps[row * PS_LD + n0] = pv;
}

// Phase B: chr = p@W for cols d0..d0+15 of `row`; update v (and x if FULL)
template <bool FULL>
__device__ __forceinline__ void phaseB(float* __restrict__ xs,
                                       float* __restrict__ vs,
                                       const float* __restrict__ ps,
                                       const float* __restrict__ W_s,
                                       const float freg[16],
                                       int row, int d0) {
    float acc[16] = {};
    #pragma unroll 2
    for (int r0 = 0; r0 < RDIM; r0 += 4) {
        float4 pa = *(const float4*)&ps[row * PS_LD + r0];
        float pp[4] = {pa.x, pa.y, pa.z, pa.w};
        #pragma unroll
        for (int kk = 0; kk < 4; kk++) {
            const float* wrow = &W_s[(r0 + kk) * DDIM + d0];
            float4 w0 = *(const float4*)&wrow[0];
            float4 w1 = *(const float4*)&wrow[4];
            float4 w2 = *(const float4*)&wrow[8];
            float4 w3 = *(const float4*)&wrow[12];
            float ww[16] = {w0.x, w0.y, w0.z, w0.w, w1.x, w1.y, w1.z, w1.w,
                            w2.x, w2.y, w2.z, w2.w, w3.x, w3.y, w3.z, w3.w};
            #pragma unroll
            for (int j = 0; j < 16; j++)
                acc[j] += pp[kk] * ww[j];
        }
    }
    const float dt  = 0.01f;
    const float hdt = 0.005f;
    float* vrow = &vs[row * XS_LD + d0];
    float* xrow = &xs[row * XS_LD + d0];
    #pragma unroll
    for (int j4 = 0; j4 < 4; j4++) {
        float4 vold = *(float4*)&vrow[j4 * 4];
        float vo[4] = {vold.x, vold.y, vold.z, vold.w};
        float vn[4];
        #pragma unroll
        for (int jj = 0; jj < 4; jj++) {
            float a = freg[j4 * 4 + jj] - acc[j4 * 4 + jj];
            vn[jj] = vo[jj] + hdt * a;
        }
        float4 vs4 = {vn[0], vn[1], vn[2], vn[3]};
        *(float4*)&vrow[j4 * 4] = vs4;
        if (FULL) {
            float4 xold = *(float4*)&xrow[j4 * 4];
            float xo[4] = {xold.x, xold.y, xold.z, xold.w};
            float xn[4];
            #pragma unroll
            for (int jj = 0; jj < 4; jj++)
                xn[jj] = wrap_torus(xo[jj] + dt * vn[jj]);
            float4 xs4 = {xn[0], xn[1], xn[2], xn[3]};
            *(float4*)&xrow[j4 * 4] = xs4;
        }
    }
}

__global__ void __launch_bounds__(THREADS, 1)
symp_kernel(const float* __restrict__ x_g, const float* __restrict__ v_g,
            const float* __restrict__ f_g, const float* __restrict__ U_g,
            const float* __restrict__ W_g, const int* __restrict__ steps_p,
            float* __restrict__ out, int B)
{
    extern __shared__ float sm[];
    float* U_s = sm;                                  // 256*64
    float* W_s = U_s + DDIM * RDIM;                   // 64*256
    float* xs  = W_s + RDIM * DDIM;                   // ROWS*XS_LD
    float* vs  = xs + ROWS * XS_LD;                   // ROWS*XS_LD
    float* ps  = vs + ROWS * XS_LD;                   // ROWS*PS_LD

    const int tid  = threadIdx.x;
    const int row0 = blockIdx.x * ROWS;

    // U, W -> SMEM (coalesced float4)
    {
        const float4* Ug4 = (const float4*)U_g;
        float4* Us4 = (float4*)U_s;
        #pragma unroll 2
        for (int i = tid; i < DDIM * RDIM / 4; i += THREADS) Us4[i] = Ug4[i];
        const float4* Wg4 = (const float4*)W_g;
        float4* Ws4 = (float4*)W_s;
        #pragma unroll 2
        for (int i = tid; i < RDIM * DDIM / 4; i += THREADS) Ws4[i] = Wg4[i];
    }
    // x, v tiles -> SMEM (padded rows)
    #pragma unroll 2
    for (int i = tid; i < ROWS * DDIM / 4; i += THREADS) {
        int m = (i * 4) / DDIM;
        int d = (i * 4) % DDIM;
        float4 xv = *(const float4*)&x_g[(size_t)(row0 + m) * DDIM + d];
        *(float4*)&xs[m * XS_LD + d] = xv;
        float4 vv = *(const float4*)&v_g[(size_t)(row0 + m) * DDIM + d];
        *(float4*)&vs[m * XS_LD + d] = vv;
    }

    const int row = tid >> 4;       // 32 rows, 1 per 16-thread group
    const int cg  = tid & 15;       // 16 col-groups
    const int n0  = cg * 4;         // phase-A cols (of 64)
    const int d0  = cg * 16;        // phase-B cols (of 256)

    // force tile in registers for all steps
    float freg[16];
    #pragma unroll
    for (int j4 = 0; j4 < 4; j4++) {
        float4 fv = *(const float4*)&f_g[(size_t)(row0 + row) * DDIM + d0 + j4 * 4];
        freg[j4 * 4 + 0] = fv.x;
        freg[j4 * 4 + 1] = fv.y;
        freg[j4 * 4 + 2] = fv.z;
        freg[j4 * 4 + 3] = fv.w;
    }

    const int S = __ldg(steps_p);
    __syncthreads();

    for (int s = 0; s < S; s++) {
        phaseA(xs, vs, ps, U_s, row, n0);            // p from (x, v)
        __syncthreads();
        phaseB<true>(xs, vs, ps, W_s, freg, row, d0); // v_half, x drift+wrap
        __syncthreads();
        phaseA(xs, vs, ps, U_s, row, n0);            // p from (x_new, v_half)
        __syncthreads();
        phaseB<false>(xs, vs, ps, W_s, freg, row, d0);// final half-kick on v
        __syncthreads();
    }

    // out = concat(x.flatten(), v.flatten())
    const size_t vbase = (size_t)B * DDIM;
    #pragma unroll 2
    for (int i = tid; i < ROWS * DDIM / 4; i += THREADS) {
        int m = (i * 4) / DDIM;
        int d = (i * 4) % DDIM;
        size_t g = (size_t)(row0 + m) * DDIM + d;
        *(float4*)&out[g]         = *(float4*)&xs[m * XS_LD + d];
        *(float4*)&out[vbase + g] = *(float4*)&vs[m * XS_LD + d];
    }
}

extern "C" void kernel_launch(void* const* d_in, const int* in_sizes, int n_in,
                              void* d_out, int out_size) {
    const float* x = (const float*)d_in[0];
    const float* v = (const float*)d_in[1];
    const float* f = (const float*)d_in[2];
    const float* U = (const float*)d_in[3];
    const float* W = (const float*)d_in[4];
    const int* steps = (const int*)d_in[5];
    float* out = (float*)d_out;

    int B  = in_sizes[0] / DDIM;
    int nb = B / ROWS;
    size_t smem = (size_t)(DDIM * RDIM + RDIM * DDIM + 2 * ROWS * XS_LD + ROWS * PS_LD)
                  * sizeof(float);  // ~202.5 KB

    cudaFuncSetAttribute(symp_kernel, cudaFuncAttributeMaxDynamicSharedMemorySize,
                         (int)smem);
    symp_kernel<<<nb, THREADS, smem>>>(x, v, f, U, W, steps, out, B);
}

// round 4
// speedup vs baseline: 3.6833x; 3.6833x over previous
#include <cuda_runtime.h>
#include <cstdint>

// Fused symplectic integrator, tensor-core edition (3xTF32 mma.sync).
// Per CTA: 32 rows for all 8 steps. GEMMs (v@U, x@U, p@W) run on
// mma.sync.m16n8k8.tf32 with hi/lo splitting for fp32-level accuracy.
// SMEM: U^T[64x260], W^T[256x68], x/v[32x260], p[32x68] — leading dims
// chosen ≡ 4 (mod 32) words so the (4q+r) fragment access pattern is
// bank-conflict-free. force lives in registers matching the C-fragment map.

#define DDIM 256
#define RDIM 64
#define ROWS 32
#define THREADS 256
#define XS_LD 260   // x/v tiles: 260 % 32 == 4 -> conflict-free a-frags
#define U_LD  260   // U^T rows (n-major)
#define W_LD  68    // W^T rows (n-major): 68 % 32 == 4
#define PS_LD 68

__device__ __forceinline__ float my_tanhf(float g) {
    float ag = fabsf(g);
    float e  = __expf(2.0f * ag);
    float t  = 1.0f - 2.0f / (e + 1.0f);
    return copysignf(t, g);
}

__device__ __forceinline__ float wrap_torus(float x) {
    const float PIf = 3.14159274101257324f;   // np.float32(np.pi)
    const float TPI = 6.28318548202514648f;
    float t = x + PIf;
    float r = fmodf(t, TPI);
    if (r < 0.0f) r += TPI;
    return r - PIf;
}

// Split fp32 into tf32 hi + tf32 lo (3xTF32 trick, CUTLASS-style).
__device__ __forceinline__ void split_tf32(float a, uint32_t& hi, uint32_t& lo) {
    asm("cvt.rna.tf32.f32 %0, %1;" : "=r"(hi) : "f"(a));
    float r = a - __uint_as_float(hi);
    asm("cvt.rna.tf32.f32 %0, %1;" : "=r"(lo) : "f"(r));
}

__device__ __forceinline__ void mma8(float c[4], const uint32_t a[4], const uint32_t b[2]) {
    asm("mma.sync.aligned.m16n8k8.row.col.f32.tf32.tf32.f32 "
        "{%0,%1,%2,%3}, {%4,%5,%6,%7}, {%8,%9}, {%0,%1,%2,%3};"
        : "+f"(c[0]), "+f"(c[1]), "+f"(c[2]), "+f"(c[3])
        : "r"(a[0]), "r"(a[1]), "r"(a[2]), "r"(a[3]), "r"(b[0]), "r"(b[1]));
}

// 3xTF32 product accumulate: c += a*b with ~fp32 accuracy
__device__ __forceinline__ void mma3(float c[4], const uint32_t ah[4], const uint32_t al[4],
                                     const uint32_t bh[2], const uint32_t bl[2]) {
    mma8(c, al, bh);
    mma8(c, ah, bl);
    mma8(c, ah, bh);
}

// Phase A: ps[32x64] = (v@U)^2 * tanh(x@U). Warp (mA, nA) covers rows mA*16..+15,
// n-tiles {nA, nA+4} (8 cols each).
__device__ __forceinline__ void phaseA(const float* __restrict__ xs,
                                       const float* __restrict__ vs,
                                       float* __restrict__ ps,
                                       const float* __restrict__ U_t,
                                       int mA, int nA, int q, int r) {
    float ch[2][4] = {}, cg[2][4] = {};
    const int ra0 = mA * 16 + q;
    const int ra1 = ra0 + 8;

    for (int k0 = 0; k0 < DDIM; k0 += 8) {
        uint32_t avh[4], avl[4], axh[4], axl[4];
        float a0 = vs[ra0 * XS_LD + k0 + r];
        float a1 = vs[ra1 * XS_LD + k0 + r];
        float a2 = vs[ra0 * XS_LD + k0 + r + 4];
        float a3 = vs[ra1 * XS_LD + k0 + r + 4];
        split_tf32(a0, avh[0], avl[0]); split_tf32(a1, avh[1], avl[1]);
        split_tf32(a2, avh[2], avl[2]); split_tf32(a3, avh[3], avl[3]);
        a0 = xs[ra0 * XS_LD + k0 + r];
        a1 = xs[ra1 * XS_LD + k0 + r];
        a2 = xs[ra0 * XS_LD + k0 + r + 4];
        a3 = xs[ra1 * XS_LD + k0 + r + 4];
        split_tf32(a0, axh[0], axl[0]); split_tf32(a1, axh[1], axl[1]);
        split_tf32(a2, axh[2], axl[2]); split_tf32(a3, axh[3], axl[3]);

        #pragma unroll
        for (int t = 0; t < 2; t++) {
            int n0 = (nA + 4 * t) * 8;
            uint32_t bh[2], bl[2];
            float b0 = U_t[(n0 + q) * U_LD + k0 + r];
            float b1 = U_t[(n0 + q) * U_LD + k0 + r + 4];
            split_tf32(b0, bh[0], bl[0]);
            split_tf32(b1, bh[1], bl[1]);
            mma3(ch[t], avh, avl, bh, bl);
            mma3(cg[t], axh, axl, bh, bl);
        }
    }
    // p = h^2 * tanh(g) -> smem
    #pragma unroll
    for (int t = 0; t < 2; t++) {
        int n0 = (nA + 4 * t) * 8;
        #pragma unroll
        for (int i = 0; i < 2; i++) {
            int row = (i ? ra1 : ra0);
            float h0 = ch[t][2 * i], h1 = ch[t][2 * i + 1];
            float g0 = cg[t][2 * i], g1 = cg[t][2 * i + 1];
            float2 p2;
            p2.x = h0 * h0 * my_tanhf(g0);
            p2.y = h1 * h1 * my_tanhf(g1);
            *(float2*)&ps[row * PS_LD + n0 + 2 * r] = p2;
        }
    }
}

// Phase B: chr = p@W; v += hdt*(f - chr); if FULL also x = wrap(x + dt*v).
// Warp (mB, wq): rows mB*16..+15, n-tiles {wq + 4j, j=0..7} (8 cols each).
template <bool FULL>
__device__ __forceinline__ void phaseB(float* __restrict__ xs,
                                       float* __restrict__ vs,
                                       const float* __restrict__ ps,
                                       const float* __restrict__ W_t,
                                       const float2 fr[8][2],
                                       int mB, int wq, int q, int r) {
    float cb[8][4];
    #pragma unroll
    for (int j = 0; j < 8; j++)
        #pragma unroll
        for (int e = 0; e < 4; e++) cb[j][e] = 0.0f;

    const int ra0 = mB * 16 + q;
    const int ra1 = ra0 + 8;

    for (int k0 = 0; k0 < RDIM; k0 += 8) {
        uint32_t ah[4], al[4];
        float a0 = ps[ra0 * PS_LD + k0 + r];
        float a1 = ps[ra1 * PS_LD + k0 + r];
        float a2 = ps[ra0 * PS_LD + k0 + r + 4];
        float a3 = ps[ra1 * PS_LD + k0 + r + 4];
        split_tf32(a0, ah[0], al[0]); split_tf32(a1, ah[1], al[1]);
        split_tf32(a2, ah[2], al[2]); split_tf32(a3, ah[3], al[3]);

        #pragma unroll
        for (int j = 0; j < 8; j++) {
            int col0 = (wq + 4 * j) * 8;
            uint32_t bh[2], bl[2];
            float b0 = W_t[(col0 + q) * W_LD + k0 + r];
            float b1 = W_t[(col0 + q) * W_LD + k0 + r + 4];
            split_tf32(b0, bh[0], bl[0]);
            split_tf32(b1, bh[1], bl[1]);
            mma3(cb[j], ah, al, bh, bl);
        }
    }

    const float dt = 0.01f, hdt = 0.005f;
    #pragma unroll
    for (int j = 0; j < 8; j++) {
        int col0 = (wq + 4 * j) * 8;
        #pragma unroll
        for (int i = 0; i < 2; i++) {
            int row = (i ? ra1 : ra0);
            float2 f2 = fr[j][i];
            float* vp = &vs[row * XS_LD + col0 + 2 * r];
            float2 vo = *(float2*)vp;
            float2 vn;
            vn.x = vo.x + hdt * (f2.x - cb[j][2 * i]);
            vn.y = vo.y + hdt * (f2.y - cb[j][2 * i + 1]);
            *(float2*)vp = vn;
            if (FULL) {
                float* xp = &xs[row * XS_LD + col0 + 2 * r];
                float2 xo = *(float2*)xp;
                float2 xn;
                xn.x = wrap_torus(xo.x + dt * vn.x);
                xn.y = wrap_torus(xo.y + dt * vn.y);
                *(float2*)xp = xn;
            }
        }
    }
}

__global__ void __launch_bounds__(THREADS, 1)
symp_kernel(const float* __restrict__ x_g, const float* __restrict__ v_g,
            const float* __restrict__ f_g, const float* __restrict__ U_g,
            const float* __restrict__ W_g, const int* __restrict__ steps_p,
            float* __restrict__ out, int B)
{
    extern __shared__ float sm[];
    float* U_t = sm;                          // 64 x 260 (n-major, transposed)
    float* W_t = U_t + RDIM * U_LD;           // 256 x 68 (n-major, transposed)
    float* xs  = W_t + DDIM * W_LD;           // 32 x 260
    float* vs  = xs + ROWS * XS_LD;           // 32 x 260
    float* ps  = vs + ROWS * XS_LD;           // 32 x 68

    const int tid  = threadIdx.x;
    const int row0 = blockIdx.x * ROWS;

    // U^T, W^T -> SMEM (reads coalesced; transposed writes are one-time)
    for (int i = tid; i < DDIM * RDIM; i += THREADS) {
        int k = i >> 6, n = i & 63;           // U[k][n]
        U_t[n * U_LD + k] = U_g[i];
    }
    for (int i = tid; i < RDIM * DDIM; i += THREADS) {
        int k = i >> 8, n = i & 255;          // W[k][n]
        W_t[n * W_LD + k] = W_g[i];
    }
    // x, v tiles -> SMEM
    for (int i = tid; i < ROWS * DDIM / 4; i += THREADS) {
        int m = (i * 4) / DDIM;
        int d = (i * 4) % DDIM;
        *(float4*)&xs[m * XS_LD + d] = *(const float4*)&x_g[(size_t)(row0 + m) * DDIM + d];
        *(float4*)&vs[m * XS_LD + d] = *(const float4*)&v_g[(size_t)(row0 + m) * DDIM + d];
    }

    const int w    = tid >> 5;
    const int lane = tid & 31;
    const int q    = lane >> 2;   // fragment group id
    const int r    = lane & 3;    // thread-in-group
    const int mA   = w >> 2;      // phase A: M-tile
    const int nA   = w & 3;       // phase A: n-tile base
    const int mB   = w & 1;       // phase B: M-tile
    const int wq   = w >> 1;      // phase B: n-tile base

    // force in registers, mapped to phase-B C-fragment coordinates
    float2 fr[8][2];
    {
        const int rb0 = row0 + mB * 16 + q;
        #pragma unroll
        for (int j = 0; j < 8; j++) {
            int col0 = (wq + 4 * j) * 8 + 2 * r;
            fr[j][0] = *(const float2*)&f_g[(size_t)rb0 * DDIM + col0];
            fr[j][1] = *(const float2*)&f_g[(size_t)(rb0 + 8) * DDIM + col0];
        }
    }

    const int S = __ldg(steps_p);
    __syncthreads();

    for (int s = 0; s < S; s++) {
        phaseA(xs, vs, ps, U_t, mA, nA, q, r);
        __syncthreads();
        phaseB<true>(xs, vs, ps, W_t, fr, mB, wq, q, r);
        __syncthreads();
        phaseA(xs, vs, ps, U_t, mA, nA, q, r);
        __syncthreads();
        phaseB<false>(xs, vs, ps, W_t, fr, mB, wq, q, r);
        __syncthreads();
    }

    // out = concat(x.flatten(), v.flatten())
    const size_t vbase = (size_t)B * DDIM;
    for (int i = tid; i < ROWS * DDIM / 4; i += THREADS) {
        int m = (i * 4) / DDIM;
        int d = (i * 4) % DDIM;
        size_t g = (size_t)(row0 + m) * DDIM + d;
        *(float4*)&out[g]         = *(float4*)&xs[m * XS_LD + d];
        *(float4*)&out[vbase + g] = *(float4*)&vs[m * XS_LD + d];
    }
}

extern "C" void kernel_launch(void* const* d_in, const int* in_sizes, int n_in,
                              void* d_out, int out_size) {
    const float* x = (const float*)d_in[0];
    const float* v = (const float*)d_in[1];
    const float* f = (const float*)d_in[2];
    const float* U = (const float*)d_in[3];
    const float* W = (const float*)d_in[4];
    const int* steps = (const int*)d_in[5];
    float* out = (float*)d_out;

    int B  = in_sizes[0] / DDIM;
    int nb = B / ROWS;
    size_t smem = (size_t)(RDIM * U_LD + DDIM * W_LD + 2 * ROWS * XS_LD + ROWS * PS_LD)
                  * sizeof(float);  // 211,456 B

    cudaFuncSetAttribute(symp_kernel, cudaFuncAttributeMaxDynamicSharedMemorySize,
                         (int)smem);
    symp_kernel<<<nb, THREADS, smem>>>(x, v, f, U, W, steps, out, B);
}

// round 5
// speedup vs baseline: 3.7121x; 1.0078x over previous
#include <cuda_runtime.h>
#include <cstdint>

// Fused symplectic integrator, 3xTF32 mma.sync, warp-specialized phase A.
// Per CTA: 32 rows, all 8 steps. 512 threads = 16 warps.
// Phase A: 16 warps = {h|g} x {2 M-tiles} x {4 n-groups}; h-warps do v@U,
// g-warps do x@U (halves per-warp loads + tf32 splits).
// p-phase: p = h^2*tanh(g), stored PRE-SPLIT (hi->hs, lo->gs, in place) so
// phase B needs no a-operand cvts.
// Phase B: 16 warps = {2 M-tiles} x {8 n-groups}, 4 n-tiles each.

#define DDIM 256
#define RDIM 64
#define ROWS 32
#define THREADS 512
#define XS_LD 260   // 260 % 32 == 4 -> conflict-free (4q+r) fragment pattern
#define U_LD  260
#define W_LD  68
#define PS_LD 68

__device__ __forceinline__ float my_tanhf(float g) {
    float ag = fabsf(g);
    float e  = __expf(2.0f * ag);
    float t  = 1.0f - 2.0f / (e + 1.0f);
    return copysignf(t, g);
}

__device__ __forceinline__ float wrap_torus(float x) {
    const float PIf = 3.14159274101257324f;
    const float TPI = 6.28318548202514648f;
    float t = x + PIf;
    float r = fmodf(t, TPI);
    if (r < 0.0f) r += TPI;
    return r - PIf;
}

__device__ __forceinline__ void split_tf32(float a, uint32_t& hi, uint32_t& lo) {
    asm("cvt.rna.tf32.f32 %0, %1;" : "=r"(hi) : "f"(a));
    float r = a - __uint_as_float(hi);
    asm("cvt.rna.tf32.f32 %0, %1;" : "=r"(lo) : "f"(r));
}

__device__ __forceinline__ void mma8(float c[4], const uint32_t a[4], const uint32_t b[2]) {
    asm("mma.sync.aligned.m16n8k8.row.col.f32.tf32.tf32.f32 "
        "{%0,%1,%2,%3}, {%4,%5,%6,%7}, {%8,%9}, {%0,%1,%2,%3};"
        : "+f"(c[0]), "+f"(c[1]), "+f"(c[2]), "+f"(c[3])
        : "r"(a[0]), "r"(a[1]), "r"(a[2]), "r"(a[3]), "r"(b[0]), "r"(b[1]));
}

__device__ __forceinline__ void mma3(float c[4], const uint32_t ah[4], const uint32_t al[4],
                                     const uint32_t bh[2], const uint32_t bl[2]) {
    mma8(c, al, bh);
    mma8(c, ah, bl);
    mma8(c, ah, bh);
}

// Phase A (one matrix): dst[32x64] += src @ U  (raw accumulation, no activation)
__device__ __forceinline__ void phaseA_one(const float* __restrict__ src,
                                           float* __restrict__ dst,
                                           const float* __restrict__ U_t,
                                           int mA, int nA, int q, int r) {
    float c[2][4] = {};
    const int ra0 = mA * 16 + q;
    const int ra1 = ra0 + 8;

    for (int k0 = 0; k0 < DDIM; k0 += 8) {
        uint32_t ah[4], al[4];
        float a0 = src[ra0 * XS_LD + k0 + r];
        float a1 = src[ra1 * XS_LD + k0 + r];
        float a2 = src[ra0 * XS_LD + k0 + r + 4];
        float a3 = src[ra1 * XS_LD + k0 + r + 4];
        split_tf32(a0, ah[0], al[0]); split_tf32(a1, ah[1], al[1]);
        split_tf32(a2, ah[2], al[2]); split_tf32(a3, ah[3], al[3]);

        #pragma unroll
        for (int t = 0; t < 2; t++) {
            int n0 = (nA + 4 * t) * 8;
            uint32_t bh[2], bl[2];
            float b0 = U_t[(n0 + q) * U_LD + k0 + r];
            float b1 = U_t[(n0 + q) * U_LD + k0 + r + 4];
            split_tf32(b0, bh[0], bl[0]);
            split_tf32(b1, bh[1], bl[1]);
            mma3(c[t], ah, al, bh, bl);
        }
    }
    #pragma unroll
    for (int t = 0; t < 2; t++) {
        int n0 = (nA + 4 * t) * 8;
        #pragma unroll
        for (int i = 0; i < 2; i++) {
            int row = (i ? ra1 : ra0);
            float2 o = {c[t][2 * i], c[t][2 * i + 1]};
            *(float2*)&dst[row * PS_LD + n0 + 2 * r] = o;
        }
    }
}

// Phase B: chr = p@W (p pre-split: hi in hs, lo in gs); update v (and x if FULL).
template <bool FULL>
__device__ __forceinline__ void phaseB(float* __restrict__ xs,
                                       float* __restrict__ vs,
                                       const float* __restrict__ hs,  // p hi
                                       const float* __restrict__ gs,  // p lo
                                       const float* __restrict__ W_t,
                                       const float2 fr[4][2],
                                       int mB, int wq, int q, int r) {
    float cb[4][4];
    #pragma unroll
    for (int j = 0; j < 4; j++)
        #pragma unroll
        for (int e = 0; e < 4; e++) cb[j][e] = 0.0f;

    const int ra0 = mB * 16 + q;
    const int ra1 = ra0 + 8;

    for (int k0 = 0; k0 < RDIM; k0 += 8) {
        uint32_t ah[4], al[4];
        ah[0] = __float_as_uint(hs[ra0 * PS_LD + k0 + r]);
        ah[1] = __float_as_uint(hs[ra1 * PS_LD + k0 + r]);
        ah[2] = __float_as_uint(hs[ra0 * PS_LD + k0 + r + 4]);
        ah[3] = __float_as_uint(hs[ra1 * PS_LD + k0 + r + 4]);
        al[0] = __float_as_uint(gs[ra0 * PS_LD + k0 + r]);
        al[1] = __float_as_uint(gs[ra1 * PS_LD + k0 + r]);
        al[2] = __float_as_uint(gs[ra0 * PS_LD + k0 + r + 4]);
        al[3] = __float_as_uint(gs[ra1 * PS_LD + k0 + r + 4]);

        #pragma unroll
        for (int j = 0; j < 4; j++) {
            int col0 = (wq + 8 * j) * 8;
            uint32_t bh[2], bl[2];
            float b0 = W_t[(col0 + q) * W_LD + k0 + r];
            float b1 = W_t[(col0 + q) * W_LD + k0 + r + 4];
            split_tf32(b0, bh[0], bl[0]);
            split_tf32(b1, bh[1], bl[1]);
            mma3(cb[j], ah, al, bh, bl);
        }
    }

    const float dt = 0.01f, hdt = 0.005f;
    #pragma unroll
    for (int j = 0; j < 4; j++) {
        int col0 = (wq + 8 * j) * 8;
        #pragma unroll
        for (int i = 0; i < 2; i++) {
            int row = (i ? ra1 : ra0);
            float2 f2 = fr[j][i];
            float* vp = &vs[row * XS_LD + col0 + 2 * r];
            float2 vo = *(float2*)vp;
            float2 vn;
            vn.x = vo.x + hdt * (f2.x - cb[j][2 * i]);
            vn.y = vo.y + hdt * (f2.y - cb[j][2 * i + 1]);
            *(float2*)vp = vn;
            if (FULL) {
                float* xp = &xs[row * XS_LD + col0 + 2 * r];
                float2 xo = *(float2*)xp;
                float2 xn;
                xn.x = wrap_torus(xo.x + dt * vn.x);
                xn.y = wrap_torus(xo.y + dt * vn.y);
                *(float2*)xp = xn;
            }
        }
    }
}

__global__ void __launch_bounds__(THREADS, 1)
symp_kernel(const float* __restrict__ x_g, const float* __restrict__ v_g,
            const float* __restrict__ f_g, const float* __restrict__ U_g,
            const float* __restrict__ W_g, const int* __restrict__ steps_p,
            float* __restrict__ out, int B)
{
    extern __shared__ float sm[];
    float* U_t = sm;                          // 64 x 260 (n-major)
    float* W_t = U_t + RDIM * U_LD;           // 256 x 68 (n-major)
    float* xs  = W_t + DDIM * W_LD;           // 32 x 260
    float* vs  = xs + ROWS * XS_LD;           // 32 x 260
    float* hs  = vs + ROWS * XS_LD;           // 32 x 68  (h, later p_hi)
    float* gs  = hs + ROWS * PS_LD;           // 32 x 68  (g, later p_lo)

    const int tid  = threadIdx.x;
    const int row0 = blockIdx.x * ROWS;

    for (int i = tid; i < DDIM * RDIM; i += THREADS) {
        int k = i >> 6, n = i & 63;           // U[k][n]
        U_t[n * U_LD + k] = U_g[i];
    }
    for (int i = tid; i < RDIM * DDIM; i += THREADS) {
        int k = i >> 8, n = i & 255;          // W[k][n]
        W_t[n * W_LD + k] = W_g[i];
    }
    for (int i = tid; i < ROWS * DDIM / 4; i += THREADS) {
        int m = (i * 4) / DDIM;
        int d = (i * 4) % DDIM;
        *(float4*)&xs[m * XS_LD + d] = *(const float4*)&x_g[(size_t)(row0 + m) * DDIM + d];
        *(float4*)&vs[m * XS_LD + d] = *(const float4*)&v_g[(size_t)(row0 + m) * DDIM + d];
    }

    const int w    = tid >> 5;
    const int lane = tid & 31;
    const int q    = lane >> 2;
    const int r    = lane & 3;
    // Phase A role: matrix (h|g), M-tile, n-group
    const int matsel = w & 1;
    const int mA     = (w >> 1) & 1;
    const int nA     = w >> 2;                // 0..3
    // Phase B role
    const int mB = w & 1;
    const int wq = w >> 1;                    // 0..7

    const float* asrcA = matsel ? xs : vs;
    float*       adstA = matsel ? gs : hs;

    // force in registers, phase-B C-fragment coordinates
    float2 fr[4][2];
    {
        const int rb0 = row0 + mB * 16 + q;
        #pragma unroll
        for (int j = 0; j < 4; j++) {
            int col0 = (wq + 8 * j) * 8 + 2 * r;
            fr[j][0] = *(const float2*)&f_g[(size_t)rb0 * DDIM + col0];
            fr[j][1] = *(const float2*)&f_g[(size_t)(rb0 + 8) * DDIM + col0];
        }
    }

    const int S = __ldg(steps_p);
    __syncthreads();

    for (int s = 0; s < 2 * S; s++) {
        // Phase A: h-warps v@U -> hs ; g-warps x@U -> gs
        phaseA_one(asrcA, adstA, U_t, mA, nA, q, r);
        __syncthreads();

        // p-phase: p = h^2 * tanh(g), stored pre-split (hi->hs, lo->gs)
        for (int i = tid; i < ROWS * RDIM; i += THREADS) {
            int row = i >> 6, k = i & 63;
            int idx = row * PS_LD + k;
            float h = hs[idx];
            float g = gs[idx];
            float p = h * h * my_tanhf(g);
            uint32_t phi, plo;
            split_tf32(p, phi, plo);
            hs[idx] = __uint_as_float(phi);
            gs[idx] = __uint_as_float(plo);
        }
        __syncthreads();

        // Phase B: full update on even s (drift+wrap), velocity-only on odd s
        if ((s & 1) == 0)
            phaseB<true>(xs, vs, hs, gs, W_t, fr, mB, wq, q, r);
        else
            phaseB<false>(xs, vs, hs, gs, W_t, fr, mB, wq, q, r);
        __syncthreads();
    }

    const size_t vbase = (size_t)B * DDIM;
    for (int i = tid; i < ROWS * DDIM / 4; i += THREADS) {
        int m = (i * 4) / DDIM;
        int d = (i * 4) % DDIM;
        size_t g = (size_t)(row0 + m) * DDIM + d;
        *(float4*)&out[g]         = *(float4*)&xs[m * XS_LD + d];
        *(float4*)&out[vbase + g] = *(float4*)&vs[m * XS_LD + d];
    }
}

extern "C" void kernel_launch(void* const* d_in, const int* in_sizes, int n_in,
                              void* d_out, int out_size) {
    const float* x = (const float*)d_in[0];
    const float* v = (const float*)d_in[1];
    const float* f = (const float*)d_in[2];
    const float* U = (const float*)d_in[3];
    const float* W = (const float*)d_in[4];
    const int* steps = (const int*)d_in[5];
    float* out = (float*)d_out;

    int B  = in_sizes[0] / DDIM;
    int nb = B / ROWS;
    size_t smem = (size_t)(RDIM * U_LD + DDIM * W_LD + 2 * ROWS * XS_LD
                           + 2 * ROWS * PS_LD) * sizeof(float);  // 220,160 B

    cudaFuncSetAttribute(symp_kernel, cudaFuncAttributeMaxDynamicSharedMemorySize,
                         (int)smem);
    symp_kernel<<<nb, THREADS, smem>>>(x, v, f, U, W, steps, out, B);
}

// round 6
// speedup vs baseline: 4.1514x; 1.1183x over previous
#include <cuda_runtime.h>
#include <cstdint>

// Fused symplectic integrator, 3xTF32 mma.sync with exact Dekker-split state.
// State x,v stored in SMEM as exact (hi,lo) pairs: hi = x & 0xFFFFE000 (valid
// tf32), lo = x - hi (exact f32). hi+lo==x exactly -> zero state drift; mma
// a-operands need NO per-read cvts. All operand splits use AND+FSUB (no cvt).
// Per CTA: 16 rows, all steps. 512 threads = 16 warps.
//   Phase A: warp = {h|g} x {8 n-tiles}: h-warps v@U, g-warps x@U.
//   p-phase: p = h^2*tanh(g), stored split (hi->hs, lo->gs).
//   Phase B: warp = 2 of 32 n-tiles; chr=p@W; update v (and x+wrap if FULL),
//            re-splitting state at write.

#define DDIM 256
#define RDIM 64
#define ROWS 16
#define THREADS 512
#define XS_LD 260   // 260 % 32 == 4 -> conflict-free (4q+r) fragment pattern
#define U_LD  260
#define W_LD  68
#define PS_LD 68
#define HIMASK 0xFFFFE000u

__device__ __forceinline__ float my_tanhf(float g) {
    float ag = fabsf(g);
    float e  = __expf(2.0f * ag);
    float t  = 1.0f - 2.0f / (e + 1.0f);
    return copysignf(t, g);
}

__device__ __forceinline__ float wrap_torus(float x) {
    const float PIf = 3.14159274101257324f;
    const float TPI = 6.28318548202514648f;
    float t = x + PIf;
    float r = fmodf(t, TPI);
    if (r < 0.0f) r += TPI;
    return r - PIf;
}

// Exact truncation split: hi = top-10-mantissa part (valid tf32), lo exact.
__device__ __forceinline__ void dsplit(float a, float& hi, float& lo) {
    hi = __uint_as_float(__float_as_uint(a) & HIMASK);
    lo = a - hi;
}

__device__ __forceinline__ void mma8(float c[4], const uint32_t a[4], const uint32_t b[2]) {
    asm("mma.sync.aligned.m16n8k8.row.col.f32.tf32.tf32.f32 "
        "{%0,%1,%2,%3}, {%4,%5,%6,%7}, {%8,%9}, {%0,%1,%2,%3};"
        : "+f"(c[0]), "+f"(c[1]), "+f"(c[2]), "+f"(c[3])
        : "r"(a[0]), "r"(a[1]), "r"(a[2]), "r"(a[3]), "r"(b[0]), "r"(b[1]));
}

__device__ __forceinline__ void mma3(float c[4], const uint32_t ah[4], const uint32_t al[4],
                                     const uint32_t bh[2], const uint32_t bl[2]) {
    mma8(c, al, bh);
    mma8(c, ah, bl);
    mma8(c, ah, bh);
}

// Phase A: dst[16x64 tile nt] = src @ U, src pre-split (sh=hi, sl=lo).
__device__ __forceinline__ void phaseA_one(const float* __restrict__ sh,
                                           const float* __restrict__ sl,
                                           float* __restrict__ dst,
                                           const float* __restrict__ U_t,
                                           int nt, int q, int r) {
    float c[4] = {};
    const int ra0 = q, ra1 = q + 8;
    const int n0 = nt * 8;

    #pragma unroll
    for (int k0 = 0; k0 < DDIM; k0 += 8) {
        uint32_t ah[4], al[4];
        ah[0] = __float_as_uint(sh[ra0 * XS_LD + k0 + r]);
        ah[1] = __float_as_uint(sh[ra1 * XS_LD + k0 + r]);
        ah[2] = __float_as_uint(sh[ra0 * XS_LD + k0 + r + 4]);
        ah[3] = __float_as_uint(sh[ra1 * XS_LD + k0 + r + 4]);
        al[0] = __float_as_uint(sl[ra0 * XS_LD + k0 + r]);
        al[1] = __float_as_uint(sl[ra1 * XS_LD + k0 + r]);
        al[2] = __float_as_uint(sl[ra0 * XS_LD + k0 + r + 4]);
        al[3] = __float_as_uint(sl[ra1 * XS_LD + k0 + r + 4]);

        float b0 = U_t[(n0 + q) * U_LD + k0 + r];
        float b1 = U_t[(n0 + q) * U_LD + k0 + r + 4];
        float bh0, bl0, bh1, bl1;
        dsplit(b0, bh0, bl0);
        dsplit(b1, bh1, bl1);
        uint32_t bh[2] = {__float_as_uint(bh0), __float_as_uint(bh1)};
        uint32_t bl[2] = {__float_as_uint(bl0), __float_as_uint(bl1)};
        mma3(c, ah, al, bh, bl);
    }
    *(float2*)&dst[ra0 * PS_LD + n0 + 2 * r] = make_float2(c[0], c[1]);
    *(float2*)&dst[ra1 * PS_LD + n0 + 2 * r] = make_float2(c[2], c[3]);
}

// Phase B: chr = p@W (p pre-split in hs/gs); update v (and x if FULL),
// re-splitting state at write. Warp covers n-tiles wq and wq+16.
template <bool FULL>
__device__ __forceinline__ void phaseB(float* __restrict__ xh, float* __restrict__ xl,
                                       float* __restrict__ vh, float* __restrict__ vl,
                                       const float* __restrict__ hs,
                                       const float* __restrict__ gs,
                                       const float* __restrict__ W_t,
                                       const float2 fr[2][2],
                                       int wq, int q, int r) {
    float cb[2][4] = {};
    const int ra0 = q, ra1 = q + 8;

    #pragma unroll
    for (int k0 = 0; k0 < RDIM; k0 += 8) {
        uint32_t ah[4], al[4];
        ah[0] = __float_as_uint(hs[ra0 * PS_LD + k0 + r]);
        ah[1] = __float_as_uint(hs[ra1 * PS_LD + k0 + r]);
        ah[2] = __float_as_uint(hs[ra0 * PS_LD + k0 + r + 4]);
        ah[3] = __float_as_uint(hs[ra1 * PS_LD + k0 + r + 4]);
        al[0] = __float_as_uint(gs[ra0 * PS_LD + k0 + r]);
        al[1] = __float_as_uint(gs[ra1 * PS_LD + k0 + r]);
        al[2] = __float_as_uint(gs[ra0 * PS_LD + k0 + r + 4]);
        al[3] = __float_as_uint(gs[ra1 * PS_LD + k0 + r + 4]);

        #pragma unroll
        for (int j = 0; j < 2; j++) {
            int col0 = (wq + 16 * j) * 8;
            float b0 = W_t[(col0 + q) * W_LD + k0 + r];
            float b1 = W_t[(col0 + q) * W_LD + k0 + r + 4];
            float bh0, bl0, bh1, bl1;
            dsplit(b0, bh0, bl0);
            dsplit(b1, bh1, bl1);
            uint32_t bh[2] = {__float_as_uint(bh0), __float_as_uint(bh1)};
            uint32_t bl[2] = {__float_as_uint(bl0), __float_as_uint(bl1)};
            mma3(cb[j], ah, al, bh, bl);
        }
    }

    const float dt = 0.01f, hdt = 0.005f;
    #pragma unroll
    for (int j = 0; j < 2; j++) {
        int col0 = (wq + 16 * j) * 8 + 2 * r;
        #pragma unroll
        for (int i = 0; i < 2; i++) {
            int row = (i ? ra1 : ra0);
            int idx = row * XS_LD + col0;
            float2 f2 = fr[j][i];
            #pragma unroll
            for (int e = 0; e < 2; e++) {
                float fv = (e ? f2.y : f2.x);
                float vo = vh[idx + e] + vl[idx + e];     // exact
                float vn = vo + hdt * (fv - cb[j][2 * i + e]);
                float nh, nl;
                dsplit(vn, nh, nl);
                vh[idx + e] = nh;
                vl[idx + e] = nl;
                if (FULL) {
                    float xo = xh[idx + e] + xl[idx + e]; // exact
                    float xn = wrap_torus(xo + dt * vn);
                    dsplit(xn, nh, nl);
                    xh[idx + e] = nh;
                    xl[idx + e] = nl;
                }
            }
        }
    }
}

__global__ void __launch_bounds__(THREADS, 1)
symp_kernel(const float* __restrict__ x_g, const float* __restrict__ v_g,
            const float* __restrict__ f_g, const float* __restrict__ U_g,
            const float* __restrict__ W_g, const int* __restrict__ steps_p,
            float* __restrict__ out, int B)
{
    extern __shared__ float sm[];
    float* U_t = sm;                          // 64 x 260 (n-major)
    float* W_t = U_t + RDIM * U_LD;           // 256 x 68 (n-major)
    float* xh  = W_t + DDIM * W_LD;           // 16 x 260
    float* xl  = xh + ROWS * XS_LD;
    float* vh  = xl + ROWS * XS_LD;
    float* vl  = vh + ROWS * XS_LD;
    float* hs  = vl + ROWS * XS_LD;           // 16 x 68
    float* gs  = hs + ROWS * PS_LD;           // 16 x 68

    const int tid  = threadIdx.x;
    const int row0 = blockIdx.x * ROWS;

    for (int i = tid; i < DDIM * RDIM; i += THREADS) {
        int k = i >> 6, n = i & 63;           // U[k][n]
        U_t[n * U_LD + k] = U_g[i];
    }
    for (int i = tid; i < RDIM * DDIM; i += THREADS) {
        int k = i >> 8, n = i & 255;          // W[k][n]
        W_t[n * W_LD + k] = W_g[i];
    }
    // x, v -> split smem state
    for (int i = tid; i < ROWS * DDIM / 4; i += THREADS) {
        int m = (i * 4) / DDIM;
        int d = (i * 4) % DDIM;
        float4 xv = *(const float4*)&x_g[(size_t)(row0 + m) * DDIM + d];
        float4 vv = *(const float4*)&v_g[(size_t)(row0 + m) * DDIM + d];
        float4 hi4, lo4;
        dsplit(xv.x, hi4.x, lo4.x); dsplit(xv.y, hi4.y, lo4.y);
        dsplit(xv.z, hi4.z, lo4.z); dsplit(xv.w, hi4.w, lo4.w);
        *(float4*)&xh[m * XS_LD + d] = hi4;
        *(float4*)&xl[m * XS_LD + d] = lo4;
        dsplit(vv.x, hi4.x, lo4.x); dsplit(vv.y, hi4.y, lo4.y);
        dsplit(vv.z, hi4.z, lo4.z); dsplit(vv.w, hi4.w, lo4.w);
        *(float4*)&vh[m * XS_LD + d] = hi4;
        *(float4*)&vl[m * XS_LD + d] = lo4;
    }

    const int w    = tid >> 5;
    const int lane = tid & 31;
    const int q    = lane >> 2;
    const int r    = lane & 3;
    const int matsel = w & 1;     // phase A: 0 -> h (v@U), 1 -> g (x@U)
    const int nt     = w >> 1;    // phase A n-tile (0..7)
    const int wq     = w;         // phase B n-tile base (0..15)

    const float* ash = matsel ? xh : vh;
    const float* asl = matsel ? xl : vl;
    float*       ad  = matsel ? gs : hs;

    // force in registers, phase-B C-fragment coordinates
    float2 fr[2][2];
    {
        #pragma unroll
        for (int j = 0; j < 2; j++) {
            int col0 = (wq + 16 * j) * 8 + 2 * r;
            fr[j][0] = *(const float2*)&f_g[(size_t)(row0 + q) * DDIM + col0];
            fr[j][1] = *(const float2*)&f_g[(size_t)(row0 + q + 8) * DDIM + col0];
        }
    }

    const int S = __ldg(steps_p);
    __syncthreads();

    for (int s = 0; s < 2 * S; s++) {
        phaseA_one(ash, asl, ad, U_t, nt, q, r);
        __syncthreads();

        // p = h^2 * tanh(g), stored split (hi->hs, lo->gs)
        for (int i = tid; i < ROWS * RDIM; i += THREADS) {
            int row = i >> 6, k = i & 63;
            int idx = row * PS_LD + k;
            float h = hs[idx];
            float g = gs[idx];
            float p = h * h * my_tanhf(g);
            float phi, plo;
            dsplit(p, phi, plo);
            hs[idx] = phi;
            gs[idx] = plo;
        }
        __syncthreads();

        if ((s & 1) == 0)
            phaseB<true>(xh, xl, vh, vl, hs, gs, W_t, fr, wq, q, r);
        else
            phaseB<false>(xh, xl, vh, vl, hs, gs, W_t, fr, wq, q, r);
        __syncthreads();
    }

    const size_t vbase = (size_t)B * DDIM;
    for (int i = tid; i < ROWS * DDIM / 4; i += THREADS) {
        int m = (i * 4) / DDIM;
        int d = (i * 4) % DDIM;
        size_t g = (size_t)(row0 + m) * DDIM + d;
        float4 a = *(float4*)&xh[m * XS_LD + d];
        float4 b = *(float4*)&xl[m * XS_LD + d];
        float4 o = {a.x + b.x, a.y + b.y, a.z + b.z, a.w + b.w};
        *(float4*)&out[g] = o;
        a = *(float4*)&vh[m * XS_LD + d];
        b = *(float4*)&vl[m * XS_LD + d];
        o = make_float4(a.x + b.x, a.y + b.y, a.z + b.z, a.w + b.w);
        *(float4*)&out[vbase + g] = o;
    }
}

extern "C" void kernel_launch(void* const* d_in, const int* in_sizes, int n_in,
                              void* d_out, int out_size) {
    const float* x = (const float*)d_in[0];
    const float* v = (const float*)d_in[1];
    const float* f = (const float*)d_in[2];
    const float* U = (const float*)d_in[3];
    const float* W = (const float*)d_in[4];
    const int* steps = (const int*)d_in[5];
    float* out = (float*)d_out;

    int B  = in_sizes[0] / DDIM;
    int nb = B / ROWS;
    size_t smem = (size_t)(RDIM * U_LD + DDIM * W_LD + 4 * ROWS * XS_LD
                           + 2 * ROWS * PS_LD) * sizeof(float);  // 211,456 B

    cudaFuncSetAttribute(symp_kernel, cudaFuncAttributeMaxDynamicSharedMemorySize,
                         (int)smem);
    symp_kernel<<<nb, THREADS, smem>>>(x, v, f, U, W, steps, out, B);
}